// round 5
// baseline (speedup 1.0000x reference)
#include <cuda_runtime.h>
#include <cstdint>
#include <cstddef>

#define NROWS 16384
#define SMEM_BYTES 71680  // 2*(128*36 + 32*136)*4

// ---------------- scratch (device globals: no allocations allowed) -------------
__device__ float  g_H1  [(size_t)NROWS * 512];   // relu(pos@W1+b1)
__device__ float  g_G   [(size_t)NROWS * 2048];  // [F | gamma]
__device__ float  g_Abuf[(size_t)NROWS * 2048];  // G @ W3[0:2048]
__device__ float  g_Bbuf[(size_t)NROWS * 2048];  // G @ W3[2048:4096]
__device__ float  g_Hbuf[(size_t)NROWS * 2048];  // relu(A + B[p] + b3)
__device__ double g_invden[512];

// ---------------- small kernels ----------------

__global__ void invden_kernel() {
    int i = threadIdx.x;
    if (i < 512) {
        // 10000^(-2i/1024) computed in double
        double e = -(2.0 * (double)i / 1024.0) * 9.210340371976184; // ln(10000)
        g_invden[i] = exp(e);
    }
}

__global__ void h1_kernel(const float* __restrict__ pos,
                          const float* __restrict__ W1,
                          const float* __restrict__ b1) {
    int k = blockIdx.x;
    int j = threadIdx.x;  // 512
    float p0 = pos[3 * k + 0];
    float p1 = pos[3 * k + 1];
    float p2 = pos[3 * k + 2];
    float v = b1[j];
    v = fmaf(p0, W1[j], v);
    v = fmaf(p1, W1[512 + j], v);
    v = fmaf(p2, W1[1024 + j], v);
    g_H1[(size_t)k * 512 + j] = fmaxf(v, 0.0f);
}

__global__ void gamma_kernel() {
    int k = blockIdx.x;
    int i = threadIdx.x;  // 512
    double ang = (double)k * g_invden[i];
    const double INV2PI = 0.15915494309189533577;
    const double TWOPI  = 6.2831853071795864769;
    double r = ang - floor(ang * INV2PI) * TWOPI;  // exact-ish range reduce in double
    float s, c;
    sincosf((float)r, &s, &c);
    float2 v; v.x = s; v.y = c;  // interleave sin,cos
    *reinterpret_cast<float2*>(g_G + (size_t)k * 2048 + 1024 + 2 * i) = v;
}

__global__ void combine_kernel(const int* __restrict__ parent,
                               const float* __restrict__ b3) {
    int k = blockIdx.x;
    int t = threadIdx.x;  // 512 threads, float4 each -> 2048 cols
    int p = parent[k];
    const float4 a  = *reinterpret_cast<const float4*>(g_Abuf + (size_t)k * 2048 + 4 * t);
    const float4 b  = *reinterpret_cast<const float4*>(g_Bbuf + (size_t)p * 2048 + 4 * t);
    const float4 bb = *reinterpret_cast<const float4*>(b3 + 4 * t);
    float4 h;
    h.x = fmaxf(a.x + b.x + bb.x, 0.0f);
    h.y = fmaxf(a.y + b.y + bb.y, 0.0f);
    h.z = fmaxf(a.z + b.z + bb.z, 0.0f);
    h.w = fmaxf(a.w + b.w + bb.w, 0.0f);
    *reinterpret_cast<float4*>(g_Hbuf + (size_t)k * 2048 + 4 * t) = h;
}

// ---------------- TF32 GEMM ----------------
// C[M,N] = A[M,Kd] * B[Kd,N] (+bias, optional relu). All row-major, fp32 in/out.
// Tile: 128x128x32, 256 threads, 8 warps in 2(M) x 4(N), warp tile 64x32,
// mma.sync.m16n8k8 tf32, double-buffered smem.

__device__ __forceinline__ uint32_t f2tf32(float x) {
    uint32_t r;
    asm("cvt.rna.tf32.f32 %0, %1;" : "=r"(r) : "f"(x));
    return r;
}

__device__ __forceinline__ void mma_tf32(float d[4], const uint32_t a[4], const uint32_t b[2]) {
    asm volatile(
        "mma.sync.aligned.m16n8k8.row.col.f32.tf32.tf32.f32 "
        "{%0,%1,%2,%3}, {%4,%5,%6,%7}, {%8,%9}, {%0,%1,%2,%3};\n"
        : "+f"(d[0]), "+f"(d[1]), "+f"(d[2]), "+f"(d[3])
        : "r"(a[0]), "r"(a[1]), "r"(a[2]), "r"(a[3]), "r"(b[0]), "r"(b[1]));
}

__global__ __launch_bounds__(256)
void gemm_tf32(const float* __restrict__ A, int lda,
               const float* __restrict__ B, int ldb,
               float* __restrict__ C, int ldc,
               int Kd,
               const float* __restrict__ bias, int do_relu) {
    extern __shared__ uint32_t smem[];
    uint32_t* sA = smem;                 // [2][128][36]  (BK+4 pad -> conflict-free frag loads)
    uint32_t* sB = smem + 2 * 128 * 36;  // [2][32][136]  (BN+8 pad -> conflict-free frag loads)

    const int tid  = threadIdx.x;
    const int lane = tid & 31;
    const int wid  = tid >> 5;
    const int g    = lane >> 2;   // groupID
    const int tig  = lane & 3;    // thread-in-group
    const int wm   = wid & 1;     // warp M (2)
    const int wn   = wid >> 1;    // warp N (4)

    const int blockM = blockIdx.y << 7;
    const int blockN = blockIdx.x << 7;

    float acc[4][4][4];
#pragma unroll
    for (int i = 0; i < 4; i++)
#pragma unroll
        for (int j = 0; j < 4; j++)
#pragma unroll
            for (int c = 0; c < 4; c++)
                acc[i][j][c] = 0.0f;

    // per-thread global-load coordinates (4 float4 of A, 4 float4 of B per tile)
    int aM[4], aK4[4], bK[4], bN4[4];
#pragma unroll
    for (int i = 0; i < 4; i++) {
        int l = tid + (i << 8);
        aM[i]  = l >> 3;          // 0..127
        aK4[i] = (l & 7) << 2;    // 0..28 step 4
        bK[i]  = l >> 5;          // 0..31
        bN4[i] = (l & 31) << 2;   // 0..124 step 4
    }

    const int tiles = Kd >> 5;
    float4 ra[4], rb[4];

    // prologue: load tile 0 -> smem buf 0
#pragma unroll
    for (int i = 0; i < 4; i++) {
        ra[i] = *reinterpret_cast<const float4*>(A + (size_t)(blockM + aM[i]) * lda + aK4[i]);
        rb[i] = *reinterpret_cast<const float4*>(B + (size_t)bK[i] * ldb + blockN + bN4[i]);
    }
#pragma unroll
    for (int i = 0; i < 4; i++) {
        uint4 va = make_uint4(f2tf32(ra[i].x), f2tf32(ra[i].y), f2tf32(ra[i].z), f2tf32(ra[i].w));
        *reinterpret_cast<uint4*>(sA + aM[i] * 36 + aK4[i]) = va;
        uint4 vb = make_uint4(f2tf32(rb[i].x), f2tf32(rb[i].y), f2tf32(rb[i].z), f2tf32(rb[i].w));
        *reinterpret_cast<uint4*>(sB + bK[i] * 136 + bN4[i]) = vb;
    }
    __syncthreads();

    int buf = 0;
    for (int kt = 0; kt < tiles; kt++) {
        if (kt + 1 < tiles) {
            int koff = (kt + 1) << 5;
#pragma unroll
            for (int i = 0; i < 4; i++) {
                ra[i] = *reinterpret_cast<const float4*>(
                    A + (size_t)(blockM + aM[i]) * lda + koff + aK4[i]);
                rb[i] = *reinterpret_cast<const float4*>(
                    B + (size_t)(koff + bK[i]) * ldb + blockN + bN4[i]);
            }
        }

        const uint32_t* cA = sA + buf * (128 * 36);
        const uint32_t* cB = sB + buf * (32 * 136);

#pragma unroll
        for (int ks = 0; ks < 4; ks++) {
            uint32_t af[4][4];
            uint32_t bfr[4][2];
            const int kc = (ks << 3) + tig;
#pragma unroll
            for (int mt = 0; mt < 4; mt++) {
                int m0 = (wm << 6) + (mt << 4) + g;
                af[mt][0] = cA[m0 * 36 + kc];
                af[mt][1] = cA[(m0 + 8) * 36 + kc];
                af[mt][2] = cA[m0 * 36 + kc + 4];
                af[mt][3] = cA[(m0 + 8) * 36 + kc + 4];
            }
#pragma unroll
            for (int nt = 0; nt < 4; nt++) {
                int n0 = (wn << 5) + (nt << 3) + g;
                bfr[nt][0] = cB[kc * 136 + n0];
                bfr[nt][1] = cB[(kc + 4) * 136 + n0];
            }
#pragma unroll
            for (int mt = 0; mt < 4; mt++)
#pragma unroll
                for (int nt = 0; nt < 4; nt++)
                    mma_tf32(acc[mt][nt], af[mt], bfr[nt]);
        }

        if (kt + 1 < tiles) {
            uint32_t* dA = sA + (buf ^ 1) * (128 * 36);
            uint32_t* dB = sB + (buf ^ 1) * (32 * 136);
#pragma unroll
            for (int i = 0; i < 4; i++) {
                uint4 va = make_uint4(f2tf32(ra[i].x), f2tf32(ra[i].y), f2tf32(ra[i].z), f2tf32(ra[i].w));
                *reinterpret_cast<uint4*>(dA + aM[i] * 36 + aK4[i]) = va;
                uint4 vb = make_uint4(f2tf32(rb[i].x), f2tf32(rb[i].y), f2tf32(rb[i].z), f2tf32(rb[i].w));
                *reinterpret_cast<uint4*>(dB + bK[i] * 136 + bN4[i]) = vb;
            }
            __syncthreads();
            buf ^= 1;
        }
    }

    // epilogue: bias (+relu), float2 stores
#pragma unroll
    for (int mt = 0; mt < 4; mt++) {
#pragma unroll
        for (int nt = 0; nt < 4; nt++) {
            int row = blockM + (wm << 6) + (mt << 4) + g;
            int col = blockN + (wn << 5) + (nt << 3) + (tig << 1);
            float bv0 = 0.0f, bv1 = 0.0f;
            if (bias) { bv0 = bias[col]; bv1 = bias[col + 1]; }
            float o0 = acc[mt][nt][0] + bv0;
            float o1 = acc[mt][nt][1] + bv1;
            float o2 = acc[mt][nt][2] + bv0;
            float o3 = acc[mt][nt][3] + bv1;
            if (do_relu) {
                o0 = fmaxf(o0, 0.0f); o1 = fmaxf(o1, 0.0f);
                o2 = fmaxf(o2, 0.0f); o3 = fmaxf(o3, 0.0f);
            }
            float2 v0; v0.x = o0; v0.y = o1;
            float2 v1; v1.x = o2; v1.y = o3;
            *reinterpret_cast<float2*>(C + (size_t)row * ldc + col)       = v0;
            *reinterpret_cast<float2*>(C + (size_t)(row + 8) * ldc + col) = v1;
        }
    }
}

// ---------------- launch ----------------

extern "C" void kernel_launch(void* const* d_in, const int* in_sizes, int n_in,
                              void* d_out, int out_size) {
    const float* pos    = (const float*)d_in[0];
    const int*   parent = (const int*)d_in[1];
    const float* W1 = (const float*)d_in[2];
    const float* b1 = (const float*)d_in[3];
    const float* W2 = (const float*)d_in[4];
    const float* b2 = (const float*)d_in[5];
    const float* W3 = (const float*)d_in[6];
    const float* b3 = (const float*)d_in[7];
    const float* W4 = (const float*)d_in[8];
    const float* b4 = (const float*)d_in[9];
    float* out = (float*)d_out;

    float *pH1, *pG, *pA, *pB, *pH;
    cudaGetSymbolAddress((void**)&pH1, g_H1);
    cudaGetSymbolAddress((void**)&pG,  g_G);
    cudaGetSymbolAddress((void**)&pA,  g_Abuf);
    cudaGetSymbolAddress((void**)&pB,  g_Bbuf);
    cudaGetSymbolAddress((void**)&pH,  g_Hbuf);
    cudaFuncSetAttribute(gemm_tf32, cudaFuncAttributeMaxDynamicSharedMemorySize, SMEM_BYTES);

    // 1) tiny per-row MLP first layer and sinusoid denominators
    invden_kernel<<<1, 512>>>();
    h1_kernel<<<NROWS, 512>>>(pos, W1, b1);
    // 2) gamma half of G
    gamma_kernel<<<NROWS, 512>>>();
    // 3) F = H1 @ W2 + b2  -> G[:, 0:1024]   ([16384,512]x[512,1024])
    gemm_tf32<<<dim3(8, 128), 256, SMEM_BYTES>>>(pH1, 512, W2, 1024, pG, 2048, 512, b2, 0);
    // 4) A = G @ W3[0:2048,:]       ([16384,2048]x[2048,2048])
    gemm_tf32<<<dim3(16, 128), 256, SMEM_BYTES>>>(pG, 2048, W3, 2048, pA, 2048, 2048, nullptr, 0);
    // 5) B = G @ W3[2048:4096,:]
    gemm_tf32<<<dim3(16, 128), 256, SMEM_BYTES>>>(pG, 2048, W3 + (size_t)2048 * 2048, 2048,
                                                  pB, 2048, 2048, nullptr, 0);
    // 6) H = relu(A + B[parent] + b3)
    combine_kernel<<<NROWS, 512>>>(parent, b3);
    // 7) out = H @ W4 + b4   ([16384,2048]x[2048,1024])
    gemm_tf32<<<dim3(8, 128), 256, SMEM_BYTES>>>(pH, 2048, W4, 1024, out, 1024, 2048, b4, 0);
}

// round 8
// speedup vs baseline: 1.4231x; 1.4231x over previous
#include <cuda_runtime.h>
#include <cstdint>
#include <cstddef>

#define NROWS 16384

// ---------------- scratch (device globals: no allocations allowed) -------------
__device__ __align__(16) float  g_H1 [(size_t)NROWS * 512];    // relu(pos@W1+b1), tf32-rounded
__device__ __align__(16) float  g_G  [(size_t)NROWS * 2048];   // [F | gamma], tf32-rounded
__device__ __align__(16) float  g_AB [(size_t)NROWS * 4096];   // GEMM2 output (unrounded)
__device__ __align__(16) float  g_H  [(size_t)NROWS * 2048];   // relu(A+B[p]+b3), tf32-rounded
__device__ __align__(16) float  g_W2r[(size_t)512  * 1024];    // rounded W2
__device__ __align__(16) float  g_W3r[(size_t)2048 * 4096];    // rounded fused [W3top|W3bot]
__device__ __align__(16) float  g_W4r[(size_t)2048 * 1024];    // rounded W4
__device__ double g_invden[512];

// ---------------- helpers ----------------

__device__ __forceinline__ uint32_t f2tf32(float x) {
    uint32_t r;
    asm("cvt.rna.tf32.f32 %0, %1;" : "=r"(r) : "f"(x));
    return r;
}
__device__ __forceinline__ float rnd(float x) { return __uint_as_float(f2tf32(x)); }

__device__ __forceinline__ uint32_t smem_u32(const void* p) {
    uint32_t a;
    asm("{ .reg .u64 t; cvta.to.shared.u64 t, %1; cvt.u32.u64 %0, t; }" : "=r"(a) : "l"(p));
    return a;
}
__device__ __forceinline__ void cp_async16(uint32_t saddr, const void* g) {
    asm volatile("cp.async.cg.shared.global [%0], [%1], 16;" :: "r"(saddr), "l"(g));
}
__device__ __forceinline__ void cp_commit() {
    asm volatile("cp.async.commit_group;" ::: "memory");
}
template<int N> __device__ __forceinline__ void cp_wait() {
    asm volatile("cp.async.wait_group %0;" :: "n"(N) : "memory");
}

__device__ __forceinline__ void mma_tf32(float d[4], const uint32_t a[4], const uint32_t b[2]) {
    asm volatile(
        "mma.sync.aligned.m16n8k8.row.col.f32.tf32.tf32.f32 "
        "{%0,%1,%2,%3}, {%4,%5,%6,%7}, {%8,%9}, {%0,%1,%2,%3};\n"
        : "+f"(d[0]), "+f"(d[1]), "+f"(d[2]), "+f"(d[3])
        : "r"(a[0]), "r"(a[1]), "r"(a[2]), "r"(a[3]), "r"(b[0]), "r"(b[1]));
}

// ---------------- small / packing kernels ----------------

__global__ void invden_kernel() {
    int i = threadIdx.x;
    if (i < 512) {
        double e = -(2.0 * (double)i / 1024.0) * 9.210340371976184; // ln(10000)
        g_invden[i] = exp(e);
    }
}

__global__ void h1_kernel(const float* __restrict__ pos,
                          const float* __restrict__ W1,
                          const float* __restrict__ b1) {
    int k = blockIdx.x;
    int j = threadIdx.x;  // 512
    float p0 = pos[3 * k + 0], p1 = pos[3 * k + 1], p2 = pos[3 * k + 2];
    float v = b1[j];
    v = fmaf(p0, W1[j], v);
    v = fmaf(p1, W1[512 + j], v);
    v = fmaf(p2, W1[1024 + j], v);
    g_H1[(size_t)k * 512 + j] = rnd(fmaxf(v, 0.0f));
}

__global__ void gamma_kernel() {
    int k = blockIdx.x;
    int i = threadIdx.x;  // 512
    double ang = (double)k * g_invden[i];
    const double INV2PI = 0.15915494309189533577;
    const double TWOPI  = 6.2831853071795864769;
    double rr = ang - floor(ang * INV2PI) * TWOPI;
    float s, c;
    sincosf((float)rr, &s, &c);
    float2 v; v.x = rnd(s); v.y = rnd(c);
    *reinterpret_cast<float2*>(g_G + (size_t)k * 2048 + 1024 + 2 * i) = v;
}

__global__ void combine_kernel(const int* __restrict__ parent,
                               const float* __restrict__ b3) {
    int k = blockIdx.x;
    int t = threadIdx.x;  // 512 threads, float4 each -> 2048 cols
    int p = parent[k];
    int c4 = 4 * t;
    const float4 a  = *reinterpret_cast<const float4*>(g_AB + (size_t)k * 4096 + c4);
    const float4 b  = *reinterpret_cast<const float4*>(g_AB + (size_t)p * 4096 + 2048 + c4);
    const float4 bb = *reinterpret_cast<const float4*>(b3 + c4);
    float4 h;
    h.x = rnd(fmaxf(a.x + b.x + bb.x, 0.0f));
    h.y = rnd(fmaxf(a.y + b.y + bb.y, 0.0f));
    h.z = rnd(fmaxf(a.z + b.z + bb.z, 0.0f));
    h.w = rnd(fmaxf(a.w + b.w + bb.w, 0.0f));
    *reinterpret_cast<float4*>(g_H + (size_t)k * 2048 + c4) = h;
}

// round a plain array (float4 granularity)
__global__ void round4_kernel(const float4* __restrict__ in, float4* __restrict__ out, int n4) {
    int i = blockIdx.x * blockDim.x + threadIdx.x;
    if (i < n4) {
        float4 v = in[i];
        v.x = rnd(v.x); v.y = rnd(v.y); v.z = rnd(v.z); v.w = rnd(v.w);
        out[i] = v;
    }
}

// fused-W3 pack: out[k][n] = rnd( n<2048 ? W3[k][n] : W3[2048+k][n-2048] )
__global__ void pack_w3_kernel(const float* __restrict__ W3) {
    int k = blockIdx.x;  // 0..2047
    float* dst = g_W3r + (size_t)k * 4096;
    const float* s0 = W3 + (size_t)k * 2048;
    const float* s1 = W3 + (size_t)(2048 + k) * 2048;
    for (int t = threadIdx.x; t < 1024; t += blockDim.x) {  // 1024 float4 per row
        int c4 = t * 4;
        const float* src = (c4 < 2048) ? (s0 + c4) : (s1 + (c4 - 2048));
        float4 v = *reinterpret_cast<const float4*>(src);
        v.x = rnd(v.x); v.y = rnd(v.y); v.z = rnd(v.z); v.w = rnd(v.w);
        *reinterpret_cast<float4*>(dst + c4) = v;
    }
}

// ---------------- TF32 GEMM (mma.sync, cp.async 3-stage) ----------------
// C[M,N] = A[M,Kd] * B[Kd,N] (+bias, optional tf32-round of output).
// All operands pre-rounded to tf32 bit patterns. Row-major.
// Tile 128x128x32, 256 threads (8 warps, 2Mx4N, warp tile 64x32).

#define STAGES    3
#define SA_STRIDE 36
#define SB_STRIDE 136
#define SA_WORDS  (128 * SA_STRIDE)                 // 4608
#define SB_WORDS  (32 * SB_STRIDE)                  // 4352
#define GEMM_SMEM (STAGES * (SA_WORDS + SB_WORDS) * 4)  // 107520 B

__global__ __launch_bounds__(256, 2)
void gemm_tf32(const float* __restrict__ A, int lda,
               const float* __restrict__ B, int ldb,
               float* __restrict__ C, int ldc,
               int Kd,
               const float* __restrict__ bias, int round_out) {
    extern __shared__ uint32_t smem[];
    uint32_t* sAw = smem;                         // [STAGES][128][36]
    uint32_t* sBw = smem + STAGES * SA_WORDS;     // [STAGES][32][136]
    const uint32_t uA = smem_u32(sAw);
    const uint32_t uB = smem_u32(sBw);

    const int tid  = threadIdx.x;
    const int lane = tid & 31;
    const int wid  = tid >> 5;
    const int g    = lane >> 2;
    const int tig  = lane & 3;
    const int wm   = wid & 1;
    const int wn   = wid >> 1;

    const int blockM = blockIdx.y << 7;
    const int blockN = blockIdx.x << 7;

    float acc[4][4][4];
#pragma unroll
    for (int i = 0; i < 4; i++)
#pragma unroll
        for (int j = 0; j < 4; j++)
#pragma unroll
            for (int c = 0; c < 4; c++)
                acc[i][j][c] = 0.0f;

    // per-thread load coords (4 float4 of A, 4 float4 of B per k-tile)
    int aM[4], aK4[4], bK[4], bN4[4];
#pragma unroll
    for (int i = 0; i < 4; i++) {
        int l = tid + (i << 8);
        aM[i]  = l >> 3;
        aK4[i] = (l & 7) << 2;
        bK[i]  = l >> 5;
        bN4[i] = (l & 31) << 2;
    }

    const int tiles = Kd >> 5;  // always >= 3 here

    // async-load one k-tile into stage s
    auto issue = [&](int kt, int s) {
        const int koff = kt << 5;
#pragma unroll
        for (int i = 0; i < 4; i++) {
            cp_async16(uA + (uint32_t)(s * SA_WORDS + aM[i] * SA_STRIDE + aK4[i]) * 4,
                       A + (size_t)(blockM + aM[i]) * lda + koff + aK4[i]);
            cp_async16(uB + (uint32_t)(s * SB_WORDS + bK[i] * SB_STRIDE + bN4[i]) * 4,
                       B + (size_t)(koff + bK[i]) * ldb + blockN + bN4[i]);
        }
    };

    // prologue
#pragma unroll
    for (int s = 0; s < STAGES; s++) {
        issue(s, s);
        cp_commit();
    }
    cp_wait<STAGES - 1>();
    __syncthreads();

    for (int kt = 0; kt < tiles; kt++) {
        const int buf = kt % STAGES;
        const uint32_t* cA = sAw + buf * SA_WORDS;
        const uint32_t* cB = sBw + buf * SB_WORDS;

#pragma unroll
        for (int ks = 0; ks < 4; ks++) {
            uint32_t af[4][4];
            uint32_t bfr[4][2];
            const int kc = (ks << 3) + tig;
#pragma unroll
            for (int mt = 0; mt < 4; mt++) {
                int m0 = (wm << 6) + (mt << 4) + g;
                af[mt][0] = cA[m0 * SA_STRIDE + kc];
                af[mt][1] = cA[(m0 + 8) * SA_STRIDE + kc];
                af[mt][2] = cA[m0 * SA_STRIDE + kc + 4];
                af[mt][3] = cA[(m0 + 8) * SA_STRIDE + kc + 4];
            }
#pragma unroll
            for (int nt = 0; nt < 4; nt++) {
                int n0 = (wn << 5) + (nt << 3) + g;
                bfr[nt][0] = cB[kc * SB_STRIDE + n0];
                bfr[nt][1] = cB[(kc + 4) * SB_STRIDE + n0];
            }
#pragma unroll
            for (int mt = 0; mt < 4; mt++)
#pragma unroll
                for (int nt = 0; nt < 4; nt++)
                    mma_tf32(acc[mt][nt], af[mt], bfr[nt]);
        }

        // refill this buffer with tile kt+STAGES
        __syncthreads();
        int nk = kt + STAGES;
        if (nk < tiles) issue(nk, buf);
        cp_commit();
        cp_wait<STAGES - 1>();
        __syncthreads();
    }

    // epilogue: bias, optional tf32 rounding, float2 stores
#pragma unroll
    for (int mt = 0; mt < 4; mt++) {
#pragma unroll
        for (int nt = 0; nt < 4; nt++) {
            int row = blockM + (wm << 6) + (mt << 4) + g;
            int col = blockN + (wn << 5) + (nt << 3) + (tig << 1);
            float bv0 = 0.0f, bv1 = 0.0f;
            if (bias) { bv0 = bias[col]; bv1 = bias[col + 1]; }
            float o0 = acc[mt][nt][0] + bv0;
            float o1 = acc[mt][nt][1] + bv1;
            float o2 = acc[mt][nt][2] + bv0;
            float o3 = acc[mt][nt][3] + bv1;
            if (round_out) {
                o0 = rnd(o0); o1 = rnd(o1); o2 = rnd(o2); o3 = rnd(o3);
            }
            float2 v0; v0.x = o0; v0.y = o1;
            float2 v1; v1.x = o2; v1.y = o3;
            *reinterpret_cast<float2*>(C + (size_t)row * ldc + col)       = v0;
            *reinterpret_cast<float2*>(C + (size_t)(row + 8) * ldc + col) = v1;
        }
    }
}

// ---------------- launch ----------------

extern "C" void kernel_launch(void* const* d_in, const int* in_sizes, int n_in,
                              void* d_out, int out_size) {
    const float* pos    = (const float*)d_in[0];
    const int*   parent = (const int*)d_in[1];
    const float* W1 = (const float*)d_in[2];
    const float* b1 = (const float*)d_in[3];
    const float* W2 = (const float*)d_in[4];
    const float* b2 = (const float*)d_in[5];
    const float* W3 = (const float*)d_in[6];
    const float* b3 = (const float*)d_in[7];
    const float* W4 = (const float*)d_in[8];
    const float* b4 = (const float*)d_in[9];
    float* out = (float*)d_out;

    float *pH1, *pG, *pAB, *pH, *pW2r, *pW3r, *pW4r;
    cudaGetSymbolAddress((void**)&pH1,  g_H1);
    cudaGetSymbolAddress((void**)&pG,   g_G);
    cudaGetSymbolAddress((void**)&pAB,  g_AB);
    cudaGetSymbolAddress((void**)&pH,   g_H);
    cudaGetSymbolAddress((void**)&pW2r, g_W2r);
    cudaGetSymbolAddress((void**)&pW3r, g_W3r);
    cudaGetSymbolAddress((void**)&pW4r, g_W4r);
    cudaFuncSetAttribute(gemm_tf32, cudaFuncAttributeMaxDynamicSharedMemorySize, GEMM_SMEM);

    // front-end: rounding + elementwise (all independent of GEMMs below them)
    invden_kernel<<<1, 512>>>();
    h1_kernel<<<NROWS, 512>>>(pos, W1, b1);
    gamma_kernel<<<NROWS, 512>>>();
    round4_kernel<<<512, 256>>>((const float4*)W2, (float4*)pW2r, 512 * 1024 / 4);
    pack_w3_kernel<<<2048, 256>>>(W3);
    round4_kernel<<<2048, 256>>>((const float4*)W4, (float4*)pW4r, 2048 * 1024 / 4);

    // GEMM1: F = H1 @ W2 + b2 -> g_G[:, 0:1024] (rounded)   [16384,512]x[512,1024]
    gemm_tf32<<<dim3(8, 128), 256, GEMM_SMEM>>>(pH1, 512, pW2r, 1024, pG, 2048, 512, b2, 1);
    // GEMM2: AB = G @ [W3top|W3bot]  [16384,2048]x[2048,4096] (unrounded)
    gemm_tf32<<<dim3(32, 128), 256, GEMM_SMEM>>>(pG, 2048, pW3r, 4096, pAB, 4096, 2048, nullptr, 0);
    // combine: H = relu(AB[k,0:2048] + AB[p,2048:4096] + b3) (rounded)
    combine_kernel<<<NROWS, 512>>>(parent, b3);
    // GEMM3: out = H @ W4 + b4   [16384,2048]x[2048,1024]
    gemm_tf32<<<dim3(8, 128), 256, GEMM_SMEM>>>(pH, 2048, pW4r, 1024, out, 1024, 2048, b4, 0);
}

// round 10
// speedup vs baseline: 1.4985x; 1.0530x over previous
#include <cuda_runtime.h>
#include <cstdint>
#include <cstddef>

#define NROWS 16384

// ---------------- scratch (device globals: no allocations allowed) -------------
// "A-format": row-major, columns permuted within each 32-col group:
//    newc = (c & ~7) | ((c & 3) << 1) | ((c >> 2) & 1)
// so (k, k+4) are adjacent -> LDS.64 fragment loads.
// "B-format": per 32-k tile: [16 pr][N n][2 e], pr=((kr>>3)<<2)|(kr&3), e=(kr>>2)&1.
__device__ __align__(16) float  g_H1 [(size_t)NROWS * 512];    // A-format
__device__ __align__(16) float  g_G  [(size_t)NROWS * 2048];   // A-format [F | gamma]
__device__ __align__(16) float  g_AB [(size_t)NROWS * 4096];   // plain row-major
__device__ __align__(16) float  g_H  [(size_t)NROWS * 2048];   // A-format
__device__ __align__(16) float  g_W2p[(size_t)512  * 1024];    // B-format
__device__ __align__(16) float  g_W3p[(size_t)2048 * 4096];    // B-format (fused W3)
__device__ __align__(16) float  g_W4p[(size_t)2048 * 1024];    // B-format
__device__ double g_invden[512];

// ---------------- helpers ----------------

__device__ __forceinline__ uint32_t f2tf32(float x) {
    uint32_t r;
    asm("cvt.rna.tf32.f32 %0, %1;" : "=r"(r) : "f"(x));
    return r;
}
__device__ __forceinline__ float rnd(float x) { return __uint_as_float(f2tf32(x)); }

__device__ __forceinline__ int apermc(int c) {  // A-format column permutation
    return (c & ~7) | ((c & 3) << 1) | ((c >> 2) & 1);
}

__device__ __forceinline__ uint32_t smem_u32(const void* p) {
    uint32_t a;
    asm("{ .reg .u64 t; cvta.to.shared.u64 t, %1; cvt.u32.u64 %0, t; }" : "=r"(a) : "l"(p));
    return a;
}
__device__ __forceinline__ void cp_async16(uint32_t saddr, const void* g) {
    asm volatile("cp.async.cg.shared.global [%0], [%1], 16;" :: "r"(saddr), "l"(g));
}
__device__ __forceinline__ void cp_commit() {
    asm volatile("cp.async.commit_group;" ::: "memory");
}
template<int N> __device__ __forceinline__ void cp_wait() {
    asm volatile("cp.async.wait_group %0;" :: "n"(N) : "memory");
}

__device__ __forceinline__ void mma_tf32(float d[4], uint2 a01, uint2 a23, uint2 b) {
    asm volatile(
        "mma.sync.aligned.m16n8k8.row.col.f32.tf32.tf32.f32 "
        "{%0,%1,%2,%3}, {%4,%5,%6,%7}, {%8,%9}, {%0,%1,%2,%3};\n"
        : "+f"(d[0]), "+f"(d[1]), "+f"(d[2]), "+f"(d[3])
        : "r"(a01.x), "r"(a23.x), "r"(a01.y), "r"(a23.y), "r"(b.x), "r"(b.y));
}

// ---------------- small / packing kernels ----------------

__global__ void invden_kernel() {
    int i = threadIdx.x;
    if (i < 512) {
        double e = -(2.0 * (double)i / 1024.0) * 9.210340371976184; // ln(10000)
        g_invden[i] = exp(e);
    }
}

__global__ void h1_kernel(const float* __restrict__ pos,
                          const float* __restrict__ W1,
                          const float* __restrict__ b1) {
    int k = blockIdx.x;
    int j = threadIdx.x;  // 512
    float p0 = pos[3 * k + 0], p1 = pos[3 * k + 1], p2 = pos[3 * k + 2];
    float v = b1[j];
    v = fmaf(p0, W1[j], v);
    v = fmaf(p1, W1[512 + j], v);
    v = fmaf(p2, W1[1024 + j], v);
    g_H1[(size_t)k * 512 + apermc(j)] = rnd(fmaxf(v, 0.0f));
}

__global__ void gamma_kernel() {
    int k = blockIdx.x;
    int i = threadIdx.x;  // 512
    double ang = (double)k * g_invden[i];
    const double INV2PI = 0.15915494309189533577;
    const double TWOPI  = 6.2831853071795864769;
    double rr = ang - floor(ang * INV2PI) * TWOPI;
    float s, c;
    sincosf((float)rr, &s, &c);
    int c0 = 1024 + 2 * i;           // even
    int n0 = apermc(c0);             // sin slot; cos slot = n0 + 2
    float* row = g_G + (size_t)k * 2048;
    row[n0]     = rnd(s);
    row[n0 + 2] = rnd(c);
}

__global__ void combine_kernel(const int* __restrict__ parent,
                               const float* __restrict__ b3) {
    int k = blockIdx.x;
    int t = threadIdx.x;  // 512 threads, 4 cols each
    int p = parent[k];
    int c4 = 4 * t;
    const float4 a  = *reinterpret_cast<const float4*>(g_AB + (size_t)k * 4096 + c4);
    const float4 b  = *reinterpret_cast<const float4*>(g_AB + (size_t)p * 4096 + 2048 + c4);
    const float4 bb = *reinterpret_cast<const float4*>(b3 + c4);
    float* row = g_H + (size_t)k * 2048;
    int base = (c4 & ~7) | ((c4 >> 2) & 1);  // apermc(c4), since c4&3==0
    row[base + 0] = rnd(fmaxf(a.x + b.x + bb.x, 0.0f));
    row[base + 2] = rnd(fmaxf(a.y + b.y + bb.y, 0.0f));
    row[base + 4] = rnd(fmaxf(a.z + b.z + bb.z, 0.0f));
    row[base + 6] = rnd(fmaxf(a.w + b.w + bb.w, 0.0f));
}

// One launch packs W2, fused-W3, W4 into B-format (tf32-rounded).
// B-format dst index for (k,n): kt=k>>5, kr=k&31, pr=((kr>>3)<<2)|(kr&3),
// e=(kr>>2)&1 -> ((kt*16+pr)*N + n)*2 + e
__global__ void pack_weights(const float* __restrict__ W2,
                             const float* __restrict__ W3,
                             const float* __restrict__ W4) {
    int b = blockIdx.x;  // 0..4607
    const float *src0 = nullptr, *src1 = nullptr;
    float* dstbase;
    int k, N;
    if (b < 512)       { k = b;        N = 1024; dstbase = g_W2p; src0 = W2 + (size_t)k * 1024; }
    else if (b < 2560) { k = b - 512;  N = 4096; dstbase = g_W3p;
                         src0 = W3 + (size_t)k * 2048;
                         src1 = W3 + (size_t)(2048 + k) * 2048; }
    else               { k = b - 2560; N = 1024; dstbase = g_W4p; src0 = W4 + (size_t)k * 1024; }
    int kt = k >> 5, kr = k & 31;
    int pr = ((kr >> 3) << 2) | (kr & 3);
    int e  = (kr >> 2) & 1;
    float* dst = dstbase + ((size_t)(kt * 16 + pr) * N) * 2 + e;
    for (int n = threadIdx.x; n < N; n += blockDim.x) {
        float v = (src1 && n >= 2048) ? src1[n - 2048] : src0[n];
        dst[(size_t)n * 2] = rnd(v);
    }
}

// ---------------- TF32 GEMM (mma.sync, cp.async 3-stage, pair layouts) ----------
// C[M,N] = A(A-format)[M,Kd] * B(B-format)[Kd,N] (+bias).
// Tile 128x128x32, 256 threads (8 warps 2Mx4N, warp tile 64x32).
// outmode 0: plain row-major. outmode 1: A-format output + tf32 round.

#define STAGES    3
#define SA_STRIDE 40                               // words/row, %32==8 -> LDS.64 conflict-free
#define SBP       264                              // words/pr-row (128n*2 + 8 pad), %32==8
#define SA_WORDS  (128 * SA_STRIDE)                // 5120
#define SB_WORDS  (16 * SBP)                       // 4224
#define GEMM_SMEM (STAGES * (SA_WORDS + SB_WORDS) * 4)  // 112128 B

__global__ __launch_bounds__(256, 2)
void gemm_tf32(const float* __restrict__ A, int lda,
               const float* __restrict__ B, int ldb,   // ldb = full N of B
               float* __restrict__ C, int ldc,
               int Kd,
               const float* __restrict__ bias, int outmode) {
    extern __shared__ uint32_t smem[];
    uint32_t* sAw = smem;
    uint32_t* sBw = smem + STAGES * SA_WORDS;
    const uint32_t uA = smem_u32(sAw);
    const uint32_t uB = smem_u32(sBw);

    const int tid  = threadIdx.x;
    const int lane = tid & 31;
    const int wid  = tid >> 5;
    const int g    = lane >> 2;
    const int tig  = lane & 3;
    const int wm   = wid & 1;
    const int wn   = wid >> 1;

    const int blockM = blockIdx.y << 7;
    const int blockN = blockIdx.x << 7;

    float acc[4][4][4];
#pragma unroll
    for (int i = 0; i < 4; i++)
#pragma unroll
        for (int j = 0; j < 4; j++)
#pragma unroll
            for (int c = 0; c < 4; c++)
                acc[i][j][c] = 0.0f;

    // per-thread cp.async coordinates
    int aM[4], aK4[4], bPr[4], bRem[4];
#pragma unroll
    for (int i = 0; i < 4; i++) {
        int l = tid + (i << 8);
        aM[i]   = l >> 3;          // 0..127
        aK4[i]  = (l & 7) << 2;    // 0..28
        bPr[i]  = l >> 6;          // 0..15
        bRem[i] = (l & 63) << 2;   // 0..252 step 4 (words)
    }

    const int tiles = Kd >> 5;

    auto issue = [&](int kt, int s) {
        const int koff = kt << 5;
        const float* Bt = B + (size_t)kt * 32 * ldb + (blockN << 1);
#pragma unroll
        for (int i = 0; i < 4; i++) {
            cp_async16(uA + (uint32_t)(s * SA_WORDS + aM[i] * SA_STRIDE + aK4[i]) * 4,
                       A + (size_t)(blockM + aM[i]) * lda + koff + aK4[i]);
            cp_async16(uB + (uint32_t)(s * SB_WORDS + bPr[i] * SBP + bRem[i]) * 4,
                       Bt + (size_t)bPr[i] * (ldb << 1) + bRem[i]);
        }
    };

    // prologue: 2 tiles in flight
    issue(0, 0); cp_commit();
    issue(1, 1); cp_commit();

    for (int kt = 0; kt < tiles; kt++) {
        cp_wait<1>();
        __syncthreads();
        {   // refill buffer used in iteration kt-1 (safe after the barrier)
            int nk = kt + 2;
            if (nk < tiles) issue(nk, nk % STAGES);
            cp_commit();
        }

        const int buf = kt % STAGES;
        const uint2* cA = reinterpret_cast<const uint2*>(sAw + buf * SA_WORDS);
        const uint2* cB = reinterpret_cast<const uint2*>(sBw + buf * SB_WORDS);

#pragma unroll
        for (int ks = 0; ks < 4; ks++) {
            uint2 a01[4], a23[4], bf[4];
#pragma unroll
            for (int mt = 0; mt < 4; mt++) {
                int m0 = (wm << 6) + (mt << 4) + g;
                int idx = m0 * (SA_STRIDE / 2) + (ks << 2) + tig;
                a01[mt] = cA[idx];
                a23[mt] = cA[idx + 8 * (SA_STRIDE / 2)];
            }
#pragma unroll
            for (int nt = 0; nt < 4; nt++) {
                int n0 = (wn << 5) + (nt << 3) + g;
                bf[nt] = cB[((ks << 2) + tig) * (SBP / 2) + n0];
            }
#pragma unroll
            for (int mt = 0; mt < 4; mt++)
#pragma unroll
                for (int nt = 0; nt < 4; nt++)
                    mma_tf32(acc[mt][nt], a01[mt], a23[mt], bf[nt]);
        }
    }

    // ---------------- epilogue ----------------
#pragma unroll
    for (int mt = 0; mt < 4; mt++) {
#pragma unroll
        for (int nt = 0; nt < 4; nt++) {
            int row = blockM + (wm << 6) + (mt << 4) + g;
            int col = blockN + (wn << 5) + (nt << 3) + (tig << 1);
            float bv0 = 0.0f, bv1 = 0.0f;
            if (bias) { bv0 = bias[col]; bv1 = bias[col + 1]; }
            float o0 = acc[mt][nt][0] + bv0;
            float o1 = acc[mt][nt][1] + bv1;
            float o2 = acc[mt][nt][2] + bv0;
            float o3 = acc[mt][nt][3] + bv1;
            if (outmode == 0) {
                float2 v0; v0.x = o0; v0.y = o1;
                float2 v1; v1.x = o2; v1.y = o3;
                *reinterpret_cast<float2*>(C + (size_t)row * ldc + col)       = v0;
                *reinterpret_cast<float2*>(C + (size_t)(row + 8) * ldc + col) = v1;
            } else {
                int nc = apermc(col);  // col+1 maps to nc+2
                float* r0 = C + (size_t)row * ldc;
                float* r1 = C + (size_t)(row + 8) * ldc;
                r0[nc]     = rnd(o0);
                r0[nc + 2] = rnd(o1);
                r1[nc]     = rnd(o2);
                r1[nc + 2] = rnd(o3);
            }
        }
    }
}

// ---------------- launch ----------------

extern "C" void kernel_launch(void* const* d_in, const int* in_sizes, int n_in,
                              void* d_out, int out_size) {
    const float* pos    = (const float*)d_in[0];
    const int*   parent = (const int*)d_in[1];
    const float* W1 = (const float*)d_in[2];
    const float* b1 = (const float*)d_in[3];
    const float* W2 = (const float*)d_in[4];
    const float* b2 = (const float*)d_in[5];
    const float* W3 = (const float*)d_in[6];
    const float* b3 = (const float*)d_in[7];
    const float* W4 = (const float*)d_in[8];
    const float* b4 = (const float*)d_in[9];
    float* out = (float*)d_out;

    float *pH1, *pG, *pAB, *pH, *pW2p, *pW3p, *pW4p;
    cudaGetSymbolAddress((void**)&pH1,  g_H1);
    cudaGetSymbolAddress((void**)&pG,   g_G);
    cudaGetSymbolAddress((void**)&pAB,  g_AB);
    cudaGetSymbolAddress((void**)&pH,   g_H);
    cudaGetSymbolAddress((void**)&pW2p, g_W2p);
    cudaGetSymbolAddress((void**)&pW3p, g_W3p);
    cudaGetSymbolAddress((void**)&pW4p, g_W4p);
    cudaFuncSetAttribute(gemm_tf32, cudaFuncAttributeMaxDynamicSharedMemorySize, GEMM_SMEM);

    // 0..3: front-end (order keeps GEMM2 at launch index 5 for ncu -s 5)
    invden_kernel<<<1, 512>>>();
    h1_kernel<<<NROWS, 512>>>(pos, W1, b1);
    gamma_kernel<<<NROWS, 512>>>();
    pack_weights<<<4608, 256>>>(W2, W3, W4);

    // 4: GEMM1: F = H1 @ W2 + b2 -> g_G[:, perm 0:1024] (A-format out)
    gemm_tf32<<<dim3(8, 128), 256, GEMM_SMEM>>>(pH1, 512, pW2p, 1024, pG, 2048, 512, b2, 1);
    // 5: GEMM2: AB = G @ [W3top|W3bot]  [16384,2048]x[2048,4096] plain
    gemm_tf32<<<dim3(32, 128), 256, GEMM_SMEM>>>(pG, 2048, pW3p, 4096, pAB, 4096, 2048, nullptr, 0);
    // 6: combine -> g_H (A-format)
    combine_kernel<<<NROWS, 512>>>(parent, b3);
    // 7: GEMM3: out = H @ W4 + b4 plain
    gemm_tf32<<<dim3(8, 128), 256, GEMM_SMEM>>>(pH, 2048, pW4p, 1024, out, 1024, 2048, b4, 0);
}